// round 6
// baseline (speedup 1.0000x reference)
#include <cuda_runtime.h>
#include <cuda_bf16.h>
#include <cstdint>

#define N_TOT   8192
#define D_DIM   256
#define B_HALF  4096
#define TILE_M  128
#define TILE_N  128
#define NJ_HALF 32                 // column tiles per half
#define K_STEPS 8                  // 256 / 32 (s8 k32 per mma)

#define ROW_BYTES 272              // 256B int8 row + 16B pad (sweeps all banks)
#define A_OFF   0
#define B0_OFF  (TILE_M * ROW_BYTES)                 // 34816
#define B1_OFF  (B0_OFF + TILE_M * ROW_BYTES)        // 69632
#define RED_OFF (B1_OFF + TILE_M * ROW_BYTES)        // 104448
#define SMEM_TOTAL (RED_OFF + 128 * 4 * 2 * 4)       // 108544

// -------- device scratch --------
__device__ __align__(16) signed char g_i8[N_TOT * D_DIM];   // quantized rows (2 MB)
__device__ int   lab_buf[N_TOT];
__device__ float part_all[2][N_TOT];
__device__ float part_pos[2][N_TOT];

// ======================= helpers =======================
static __device__ __forceinline__ uint32_t smem_u32(const void* p) {
    uint32_t a;
    asm("{ .reg .u64 t; cvta.to.shared.u64 t, %1; cvt.u32.u64 %0, t; }" : "=r"(a) : "l"(p));
    return a;
}
static __device__ __forceinline__ float ex2f(float x) {
    float r; asm("ex2.approx.ftz.f32 %0, %1;" : "=f"(r) : "f"(x)); return r;
}
static __device__ __forceinline__ void cp16(uint32_t saddr, const void* g) {
    asm volatile("cp.async.cg.shared.global [%0], [%1], 16;" :: "r"(saddr), "l"(g) : "memory");
}
#define CP_COMMIT() asm volatile("cp.async.commit_group;" ::: "memory")
#define CP_WAIT(n)  asm volatile("cp.async.wait_group %0;" :: "n"(n) : "memory")

static __device__ __forceinline__ void ldsm_x4(uint32_t& r0, uint32_t& r1,
                                               uint32_t& r2, uint32_t& r3, uint32_t a) {
    asm volatile("ldmatrix.sync.aligned.m8n8.x4.shared.b16 {%0,%1,%2,%3}, [%4];"
                 : "=r"(r0), "=r"(r1), "=r"(r2), "=r"(r3) : "r"(a));
}
// int8 m16n8k32: D(s32x4) = A(s8x16) * B(s8x8) + C
static __device__ __forceinline__ void mma16832(int* d, const uint32_t* a,
                                                uint32_t b0, uint32_t b1) {
    asm volatile(
        "mma.sync.aligned.m16n8k32.row.col.s32.s8.s8.s32 "
        "{%0,%1,%2,%3}, {%4,%5,%6,%7}, {%8,%9}, {%0,%1,%2,%3};"
        : "+r"(d[0]), "+r"(d[1]), "+r"(d[2]), "+r"(d[3])
        : "r"(a[0]), "r"(a[1]), "r"(a[2]), "r"(a[3]), "r"(b0), "r"(b1));
}

// ============================================================================
// Kernel 1: L2-normalize rows, quantize to int8 (scale 127), copy labels.
// One warp per row. Lane covers elements 8*lane .. 8*lane+7.
// ============================================================================
__global__ void prep_kernel(const float* __restrict__ feats,
                            const float* __restrict__ posf,
                            const int* __restrict__ labels) {
    int row  = blockIdx.x * 8 + (threadIdx.x >> 5);
    int lane = threadIdx.x & 31;
    const float* src = (row < B_HALF) ? (feats + (size_t)row * D_DIM)
                                      : (posf + (size_t)(row - B_HALF) * D_DIM);
    const float4* s4 = reinterpret_cast<const float4*>(src);
    float4 v0 = s4[2 * lane];
    float4 v1 = s4[2 * lane + 1];
    float ss = v0.x*v0.x + v0.y*v0.y + v0.z*v0.z + v0.w*v0.w
             + v1.x*v1.x + v1.y*v1.y + v1.z*v1.z + v1.w*v1.w;
    #pragma unroll
    for (int off = 16; off > 0; off >>= 1)
        ss += __shfl_xor_sync(0xffffffffu, ss, off);
    float q = 127.0f * rsqrtf(ss);

    int q0 = __float2int_rn(v0.x * q), q1 = __float2int_rn(v0.y * q);
    int q2 = __float2int_rn(v0.z * q), q3 = __float2int_rn(v0.w * q);
    int q4 = __float2int_rn(v1.x * q), q5 = __float2int_rn(v1.y * q);
    int q6 = __float2int_rn(v1.z * q), q7 = __float2int_rn(v1.w * q);
    uint2 o;
    o.x = (uint32_t)(q0 & 255) | ((uint32_t)(q1 & 255) << 8)
        | ((uint32_t)(q2 & 255) << 16) | ((uint32_t)q3 << 24);
    o.y = (uint32_t)(q4 & 255) | ((uint32_t)(q5 & 255) << 8)
        | ((uint32_t)(q6 & 255) << 16) | ((uint32_t)q7 << 24);
    reinterpret_cast<uint2*>(g_i8 + (size_t)row * D_DIM)[lane] = o;
    if (lane == 0)
        lab_buf[row] = labels[(row < B_HALF) ? row : row - B_HALF];
}

// issue async copy of one 128x256 int8 tile into smem (row stride 272B)
static __device__ __forceinline__ void issue_tile(uint32_t sbuf, int row0, int tid) {
    const char* src = reinterpret_cast<const char*>(g_i8);
    #pragma unroll
    for (int t = 0; t < 8; t++) {
        int id = tid + t * 256;
        int r  = id >> 4;            // 0..127
        int kc = id & 15;            // 16B chunk
        cp16(sbuf + r * ROW_BYTES + kc * 16,
             src + (size_t)(row0 + r) * D_DIM + kc * 16);
    }
}

// ============================================================================
// MMA for one 128x128 tile into the given acc set (zeroed here). int8 k32.
// ============================================================================
static __device__ __forceinline__ void mma_tile(int (&acc)[4][4][4],
                                                uint32_t a_lane, uint32_t b_lane) {
    #pragma unroll
    for (int ms = 0; ms < 4; ms++)
        #pragma unroll
        for (int ns = 0; ns < 4; ns++)
            #pragma unroll
            for (int c = 0; c < 4; c++) acc[ms][ns][c] = 0;

    #pragma unroll
    for (int ks = 0; ks < K_STEPS; ks++) {
        const uint32_t koff = (uint32_t)(ks * 32);
        uint32_t a[4][4];
        #pragma unroll
        for (int ms = 0; ms < 4; ms++)
            ldsm_x4(a[ms][0], a[ms][1], a[ms][2], a[ms][3],
                    a_lane + (uint32_t)(ms * 16 * ROW_BYTES) + koff);
        uint32_t b[2][4];
        #pragma unroll
        for (int p = 0; p < 2; p++)
            ldsm_x4(b[p][0], b[p][1], b[p][2], b[p][3],
                    b_lane + (uint32_t)(p * 16 * ROW_BYTES) + koff);
        // x4 at col window 16p: r0/r2 = b0/b1 of ns=2p ; r1/r3 = b0/b1 of ns=2p+1
        #pragma unroll
        for (int ms = 0; ms < 4; ms++) {
            mma16832(acc[ms][0], a[ms], b[0][0], b[0][2]);
            mma16832(acc[ms][1], a[ms], b[0][1], b[0][3]);
            mma16832(acc[ms][2], a[ms], b[1][0], b[1][2]);
            mma16832(acc[ms][3], a[ms], b[1][1], b[1][3]);
        }
    }
}

// ============================================================================
// Epilogue: dequant + exp + (diag)/label masked accumulation.
// ============================================================================
template <bool DIAG>
static __device__ __forceinline__ void epilogue(const int (&acc)[4][4][4],
        int i0, int wm, int wn, int lane, int jbase,
        const int (&labr)[8], float (&sall)[8], float (&spos)[8]) {
    // log2(e) / tau / 127^2
    const float K_EXP = 14.42695040888963f / 16129.0f;
    int labc[4][2];
    #pragma unroll
    for (int ns = 0; ns < 4; ns++) {
        int c0 = jbase + wn * 32 + ns * 8 + (lane & 3) * 2;
        labc[ns][0] = lab_buf[c0];
        labc[ns][1] = lab_buf[c0 + 1];
    }
    #pragma unroll
    for (int ms = 0; ms < 4; ms++) {
        const int gi_lo = i0 + wm * 64 + ms * 16 + (lane >> 2);
        #pragma unroll
        for (int ns = 0; ns < 4; ns++) {
            const int gj0 = jbase + wn * 32 + ns * 8 + (lane & 3) * 2;
            #pragma unroll
            for (int c = 0; c < 4; c++) {
                const int rh   = c >> 1;
                const int slot = ms * 2 + rh;
                float e = ex2f(__int2float_rn(acc[ms][ns][c]) * K_EXP);
                bool ok = true;
                if (DIAG) ok = (gi_lo + rh * 8) != (gj0 + (c & 1));
                if (ok) {
                    sall[slot] += e;
                    if (labc[ns][c & 1] == labr[slot]) spos[slot] += e;
                }
            }
        }
    }
}

// ============================================================================
// Kernel 2: int8 MMA gram, pipelined: MMA(tile jt) overlaps epilogue(jt-1).
// Grid = 128 CTAs (64 row-tiles x 2 halves), 256 threads (8 warps).
// ============================================================================
__global__ void __launch_bounds__(256, 1) milnce_mma_kernel() {
    extern __shared__ char smem[];
    const uint32_t sb = smem_u32(smem);

    const int tid  = threadIdx.x;
    const int wid  = tid >> 5;
    const int lane = tid & 31;
    const int wm   = wid >> 2;          // 0..1
    const int wn   = wid & 3;           // 0..3
    const int rt   = blockIdx.x >> 1;
    const int half = blockIdx.x & 1;
    const int i0   = rt * TILE_M;
    const int jhb  = half * (NJ_HALF * TILE_N);

    const int lrow16 = (lane & 7) + ((lane >> 3) & 1) * 8;   // row/col within 16
    const int lkb    = (lane >> 4) * 16;                     // byte half of 32B chunk

    const uint32_t a_lane  = sb + A_OFF + (uint32_t)((wm * 64 + lrow16) * ROW_BYTES + lkb);
    const uint32_t b_off   = (uint32_t)((wn * 32 + lrow16) * ROW_BYTES + lkb);
    const uint32_t b0_lane = sb + B0_OFF + b_off;
    const uint32_t b1_lane = sb + B1_OFF + b_off;

    // prologue: A + B0 (group 0), B1 (group 1)
    issue_tile(sb + A_OFF, i0, tid);
    issue_tile(sb + B0_OFF, jhb + 0 * TILE_N, tid);
    CP_COMMIT();
    issue_tile(sb + B1_OFF, jhb + 1 * TILE_N, tid);
    CP_COMMIT();

    int labr[8];
    #pragma unroll
    for (int s = 0; s < 8; s++)
        labr[s] = lab_buf[i0 + wm * 64 + (s >> 1) * 16 + (s & 1) * 8 + (lane >> 2)];

    float sall[8] = {0,0,0,0,0,0,0,0};
    float spos[8] = {0,0,0,0,0,0,0,0};

    int accA[4][4][4], accB[4][4][4];

    // ---- iter 0: MMA tile 0 into accA ----
    CP_WAIT(1);
    __syncthreads();
    mma_tile(accA, a_lane, b0_lane);
    __syncthreads();
    issue_tile(sb + B0_OFF, jhb + 2 * TILE_N, tid);
    CP_COMMIT();

    // ---- steady state ----
    #pragma unroll 1
    for (int jt = 1; jt < NJ_HALF - 1; jt += 2) {
        CP_WAIT(1);
        __syncthreads();
        mma_tile(accB, a_lane, b1_lane);
        __syncthreads();
        if (jt + 2 < NJ_HALF) { issue_tile(sb + B1_OFF, jhb + (jt + 2) * TILE_N, tid); CP_COMMIT(); }
        {
            const int jb = jhb + (jt - 1) * TILE_N;
            if (jb == i0) epilogue<true >(accA, i0, wm, wn, lane, jb, labr, sall, spos);
            else          epilogue<false>(accA, i0, wm, wn, lane, jb, labr, sall, spos);
        }
        CP_WAIT(1);
        __syncthreads();
        mma_tile(accA, a_lane, b0_lane);
        __syncthreads();
        if (jt + 3 < NJ_HALF) { issue_tile(sb + B0_OFF, jhb + (jt + 3) * TILE_N, tid); CP_COMMIT(); }
        {
            const int jb = jhb + jt * TILE_N;
            if (jb == i0) epilogue<true >(accB, i0, wm, wn, lane, jb, labr, sall, spos);
            else          epilogue<false>(accB, i0, wm, wn, lane, jb, labr, sall, spos);
        }
    }

    // ---- peel tile 31 ----
    CP_WAIT(0);
    __syncthreads();
    mma_tile(accB, a_lane, b1_lane);
    {
        const int jb = jhb + (NJ_HALF - 2) * TILE_N;
        if (jb == i0) epilogue<true >(accA, i0, wm, wn, lane, jb, labr, sall, spos);
        else          epilogue<false>(accA, i0, wm, wn, lane, jb, labr, sall, spos);
    }
    {
        const int jb = jhb + (NJ_HALF - 1) * TILE_N;
        if (jb == i0) epilogue<true >(accB, i0, wm, wn, lane, jb, labr, sall, spos);
        else          epilogue<false>(accB, i0, wm, wn, lane, jb, labr, sall, spos);
    }

    // ---- reduction: quad shfl -> smem cross-warp -> global ----
    #pragma unroll
    for (int s = 0; s < 8; s++) {
        sall[s] += __shfl_xor_sync(0xffffffffu, sall[s], 1);
        sall[s] += __shfl_xor_sync(0xffffffffu, sall[s], 2);
        spos[s] += __shfl_xor_sync(0xffffffffu, spos[s], 1);
        spos[s] += __shfl_xor_sync(0xffffffffu, spos[s], 2);
    }
    float* red_all = reinterpret_cast<float*>(smem + RED_OFF);          // [128][4]
    float* red_pos = red_all + 128 * 4;                                 // [128][4]
    __syncthreads();
    if ((lane & 3) == 0) {
        #pragma unroll
        for (int s = 0; s < 8; s++) {
            int rloc = wm * 64 + (s >> 1) * 16 + (s & 1) * 8 + (lane >> 2);
            red_all[rloc * 4 + wn] = sall[s];
            red_pos[rloc * 4 + wn] = spos[s];
        }
    }
    __syncthreads();
    if (tid < 128) {
        float a = red_all[tid * 4 + 0] + red_all[tid * 4 + 1]
                + red_all[tid * 4 + 2] + red_all[tid * 4 + 3];
        float p = red_pos[tid * 4 + 0] + red_pos[tid * 4 + 1]
                + red_pos[tid * 4 + 2] + red_pos[tid * 4 + 3];
        part_all[half][i0 + tid] = a;
        part_pos[half][i0 + tid] = p;
    }
}

// ============================================================================
// Kernel 3: loss = sum_i [ log(S_all_i) - log(S_pos_i) ]
// ============================================================================
__global__ void finalize_kernel(float* __restrict__ out) {
    __shared__ float red[256];
    float s = 0.f;
    for (int i = threadIdx.x; i < N_TOT; i += 256) {
        float a = part_all[0][i] + part_all[1][i];
        float p = part_pos[0][i] + part_pos[1][i];
        s += logf(a) - logf(p);
    }
    red[threadIdx.x] = s;
    __syncthreads();
    for (int o = 128; o > 0; o >>= 1) {
        if (threadIdx.x < o) red[threadIdx.x] += red[threadIdx.x + o];
        __syncthreads();
    }
    if (threadIdx.x == 0) out[0] = red[0];
}

// ============================================================================
extern "C" void kernel_launch(void* const* d_in, const int* in_sizes, int n_in,
                              void* d_out, int out_size) {
    const float* feats  = (const float*)d_in[0];
    const float* posf   = (const float*)d_in[1];
    const int*   labels = (const int*)d_in[2];

    prep_kernel<<<N_TOT / 8, 256>>>(feats, posf, labels);

    cudaFuncSetAttribute(milnce_mma_kernel,
                         cudaFuncAttributeMaxDynamicSharedMemorySize, SMEM_TOTAL);
    milnce_mma_kernel<<<128, 256, SMEM_TOTAL>>>();

    finalize_kernel<<<1, 256>>>((float*)d_out);
}

// round 7
// speedup vs baseline: 3.0035x; 3.0035x over previous
#include <cuda_runtime.h>
#include <cuda_bf16.h>
#include <cstdint>

#define N_TOT   8192
#define D_DIM   256
#define B_HALF  4096
#define TILE_M  128
#define NROWT   64                 // 128-row tiles
#define K_STEPS 16                 // 256 / 16

#define ROW_BYTES 528              // 264 bf16 row pitch (bank-conflict-free ldmatrix)
#define A_OFF   0
#define B0_OFF  (TILE_M * ROW_BYTES)                 // 67584
#define B1_OFF  (B0_OFF + TILE_M * ROW_BYTES)        // 135168
#define RED_OFF (B1_OFF + TILE_M * ROW_BYTES)        // 202752
#define SMEM_TOTAL (RED_OFF + 128 * 4 * 2 * 4)       // 206848

// -------- device scratch --------
__device__ __align__(16) __nv_bfloat16 g_bf[N_TOT * D_DIM];   // normalized bf16 (4 MB)
__device__ int   lab_buf[N_TOT];

// partial-sum scratch (zeroed in prep):
//   part_row_all[4][8192], part_row_pos[4][8192]      (chunk slots)
//   part_col_all[128][8192], part_col_pos[128][8192]  (slot = it*2 + wm)
#define PR_ALL  0
#define PR_POS  (4 * N_TOT)
#define PC_ALL  (8 * N_TOT)
#define PC_POS  (PC_ALL + 128 * N_TOT)
#define SCRATCH_FLOATS (PC_POS + 128 * N_TOT)          // 2,162,688 floats
__device__ __align__(16) float scratch[SCRATCH_FLOATS];
__device__ float rowloss[N_TOT];

// ======================= helpers =======================
static __device__ __forceinline__ uint32_t smem_u32(const void* p) {
    uint32_t a;
    asm("{ .reg .u64 t; cvta.to.shared.u64 t, %1; cvt.u32.u64 %0, t; }" : "=r"(a) : "l"(p));
    return a;
}
static __device__ __forceinline__ float ex2f(float x) {
    float r; asm("ex2.approx.ftz.f32 %0, %1;" : "=f"(r) : "f"(x)); return r;
}
static __device__ __forceinline__ uint32_t pack_bf2(float lo, float hi) {
    uint32_t r; asm("cvt.rn.bf16x2.f32 %0, %1, %2;" : "=r"(r) : "f"(hi), "f"(lo)); return r;
}
static __device__ __forceinline__ void cp16(uint32_t saddr, const void* g) {
    asm volatile("cp.async.cg.shared.global [%0], [%1], 16;" :: "r"(saddr), "l"(g) : "memory");
}
#define CP_COMMIT() asm volatile("cp.async.commit_group;" ::: "memory")
#define CP_WAIT(n)  asm volatile("cp.async.wait_group %0;" :: "n"(n) : "memory")

static __device__ __forceinline__ void ldsm_x4(uint32_t& r0, uint32_t& r1,
                                               uint32_t& r2, uint32_t& r3, uint32_t a) {
    asm volatile("ldmatrix.sync.aligned.m8n8.x4.shared.b16 {%0,%1,%2,%3}, [%4];"
                 : "=r"(r0), "=r"(r1), "=r"(r2), "=r"(r3) : "r"(a));
}
static __device__ __forceinline__ void mma16816(float* d, const uint32_t* a,
                                                uint32_t b0, uint32_t b1) {
    asm volatile(
        "mma.sync.aligned.m16n8k16.row.col.f32.bf16.bf16.f32 "
        "{%0,%1,%2,%3}, {%4,%5,%6,%7}, {%8,%9}, {%0,%1,%2,%3};"
        : "+f"(d[0]), "+f"(d[1]), "+f"(d[2]), "+f"(d[3])
        : "r"(a[0]), "r"(a[1]), "r"(a[2]), "r"(a[3]), "r"(b0), "r"(b1));
}

// ============================================================================
// Kernel 1: normalize rows -> bf16, labels, and zero the partial-sum scratch.
// ============================================================================
__global__ void prep_kernel(const float* __restrict__ feats,
                            const float* __restrict__ posf,
                            const int* __restrict__ labels) {
    int row  = blockIdx.x * 8 + (threadIdx.x >> 5);
    int lane = threadIdx.x & 31;
    const float* src = (row < B_HALF) ? (feats + (size_t)row * D_DIM)
                                      : (posf + (size_t)(row - B_HALF) * D_DIM);
    const float4* s4 = reinterpret_cast<const float4*>(src);
    float4 v0 = s4[lane];
    float4 v1 = s4[lane + 32];
    float ss = v0.x*v0.x + v0.y*v0.y + v0.z*v0.z + v0.w*v0.w
             + v1.x*v1.x + v1.y*v1.y + v1.z*v1.z + v1.w*v1.w;
    #pragma unroll
    for (int off = 16; off > 0; off >>= 1)
        ss += __shfl_xor_sync(0xffffffffu, ss, off);
    float inv = rsqrtf(ss);
    uint2 o0, o1;
    o0.x = pack_bf2(v0.x * inv, v0.y * inv);
    o0.y = pack_bf2(v0.z * inv, v0.w * inv);
    o1.x = pack_bf2(v1.x * inv, v1.y * inv);
    o1.y = pack_bf2(v1.z * inv, v1.w * inv);
    uint2* dst = reinterpret_cast<uint2*>(g_bf + (size_t)row * D_DIM);
    dst[lane]      = o0;
    dst[lane + 32] = o1;
    if (lane == 0)
        lab_buf[row] = labels[(row < B_HALF) ? row : row - B_HALF];

    // zero scratch (grid-stride float4)
    float4* z = reinterpret_cast<float4*>(scratch);
    const int nz = SCRATCH_FLOATS / 4;
    const float4 zero4 = make_float4(0.f, 0.f, 0.f, 0.f);
    for (int i = blockIdx.x * blockDim.x + threadIdx.x; i < nz; i += gridDim.x * blockDim.x)
        z[i] = zero4;
}

// issue async copy of one 128x256 bf16 tile into smem (row stride 528B)
static __device__ __forceinline__ void issue_tile(uint32_t sbuf, int row0, int tid) {
    const uint4* src = reinterpret_cast<const uint4*>(g_bf);
    #pragma unroll
    for (int t = 0; t < 16; t++) {
        int id = tid + t * 256;
        int r  = id >> 5;
        int kc = id & 31;
        cp16(sbuf + r * ROW_BYTES + kc * 16, src + (size_t)(row0 + r) * 32 + kc);
    }
}

// ============================================================================
// MMA for one 128x128 tile (zeroed acc).
// ============================================================================
static __device__ __forceinline__ void mma_tile(float (&acc)[4][4][4],
                                                uint32_t a_lane, uint32_t b_lane) {
    #pragma unroll
    for (int ms = 0; ms < 4; ms++)
        #pragma unroll
        for (int ns = 0; ns < 4; ns++)
            #pragma unroll
            for (int c = 0; c < 4; c++) acc[ms][ns][c] = 0.f;

    #pragma unroll 2
    for (int ks = 0; ks < K_STEPS; ks++) {
        const uint32_t koff = (uint32_t)(ks * 32);
        uint32_t a[4][4];
        #pragma unroll
        for (int ms = 0; ms < 4; ms++)
            ldsm_x4(a[ms][0], a[ms][1], a[ms][2], a[ms][3],
                    a_lane + (uint32_t)(ms * 16 * ROW_BYTES) + koff);
        uint32_t b[2][4];
        #pragma unroll
        for (int p = 0; p < 2; p++)
            ldsm_x4(b[p][0], b[p][1], b[p][2], b[p][3],
                    b_lane + (uint32_t)(p * 16 * ROW_BYTES) + koff);
        #pragma unroll
        for (int ms = 0; ms < 4; ms++) {
            mma16816(acc[ms][0], a[ms], b[0][0], b[0][2]);
            mma16816(acc[ms][1], a[ms], b[0][1], b[0][3]);
            mma16816(acc[ms][2], a[ms], b[1][0], b[1][2]);
            mma16816(acc[ms][3], a[ms], b[1][1], b[1][3]);
        }
    }
}

// ============================================================================
// Epilogue. DIAG: diagonal tile (mask i==j, row sums only).
// Off-diag: row sums + column sums (written to part_col slot it*2+wm).
// ============================================================================
template <bool DIAG>
static __device__ __forceinline__ void epilogue(const float (&acc)[4][4][4],
        int i0, int it, int jt, int wm, int wn, int lane,
        const int (&labr)[8], float (&sall)[8], float (&spos)[8]) {
    const float K_EXP = 14.42695040888963f;   // log2(e)/tau
    const int jbase = jt * TILE_M;
    int labc[4][2];
    #pragma unroll
    for (int ns = 0; ns < 4; ns++) {
        int c0 = jbase + wn * 32 + ns * 8 + (lane & 3) * 2;
        labc[ns][0] = lab_buf[c0];
        labc[ns][1] = lab_buf[c0 + 1];
    }
    float ecall[8], ecpos[8];
    #pragma unroll
    for (int x = 0; x < 8; x++) { ecall[x] = 0.f; ecpos[x] = 0.f; }

    #pragma unroll
    for (int ms = 0; ms < 4; ms++) {
        const int gi_lo = i0 + wm * 64 + ms * 16 + (lane >> 2);
        #pragma unroll
        for (int ns = 0; ns < 4; ns++) {
            const int gj0 = jbase + wn * 32 + ns * 8 + (lane & 3) * 2;
            #pragma unroll
            for (int c = 0; c < 4; c++) {
                const int rh   = c >> 1;
                const int slot = ms * 2 + rh;
                const int b    = c & 1;
                float e = ex2f(acc[ms][ns][c] * K_EXP);
                bool match = (labc[ns][b] == labr[slot]);
                if (DIAG) {
                    if ((gi_lo + rh * 8) != (gj0 + b)) {
                        sall[slot] += e;
                        if (match) spos[slot] += e;
                    }
                } else {
                    sall[slot] += e;
                    ecall[ns * 2 + b] += e;
                    if (match) { spos[slot] += e; ecpos[ns * 2 + b] += e; }
                }
            }
        }
    }

    if (!DIAG) {
        // reduce col partials across the 8 lanes sharing (lane & 3)
        #pragma unroll
        for (int x = 0; x < 8; x++) {
            #pragma unroll
            for (int off = 4; off < 32; off <<= 1) {
                ecall[x] += __shfl_xor_sync(0xffffffffu, ecall[x], off);
                ecpos[x] += __shfl_xor_sync(0xffffffffu, ecpos[x], off);
            }
        }
        if (lane < 4) {
            const int slot = it * 2 + wm;
            float2* pa = reinterpret_cast<float2*>(scratch + PC_ALL + (size_t)slot * N_TOT);
            float2* pp = reinterpret_cast<float2*>(scratch + PC_POS + (size_t)slot * N_TOT);
            #pragma unroll
            for (int ns = 0; ns < 4; ns++) {
                int cidx = (jbase + wn * 32 + ns * 8 + lane * 2) >> 1;
                pa[cidx] = make_float2(ecall[ns * 2], ecall[ns * 2 + 1]);
                pp[cidx] = make_float2(ecpos[ns * 2], ecpos[ns * 2 + 1]);
            }
        }
    }
}

// flush accumulated row sums for the current row block into part_row slot q
static __device__ __forceinline__ void flush_rows(char* smem, float (&sall)[8],
        float (&spos)[8], int i0, int q, int wm, int wn, int lane, int tid) {
    #pragma unroll
    for (int s = 0; s < 8; s++) {
        sall[s] += __shfl_xor_sync(0xffffffffu, sall[s], 1);
        sall[s] += __shfl_xor_sync(0xffffffffu, sall[s], 2);
        spos[s] += __shfl_xor_sync(0xffffffffu, spos[s], 1);
        spos[s] += __shfl_xor_sync(0xffffffffu, spos[s], 2);
    }
    float* red_all = reinterpret_cast<float*>(smem + RED_OFF);   // [128][4]
    float* red_pos = red_all + 128 * 4;
    __syncthreads();
    if ((lane & 3) == 0) {
        #pragma unroll
        for (int s = 0; s < 8; s++) {
            int rloc = wm * 64 + (s >> 1) * 16 + (s & 1) * 8 + (lane >> 2);
            red_all[rloc * 4 + wn] = sall[s];
            red_pos[rloc * 4 + wn] = spos[s];
        }
    }
    __syncthreads();
    if (tid < 128) {
        float a = red_all[tid * 4 + 0] + red_all[tid * 4 + 1]
                + red_all[tid * 4 + 2] + red_all[tid * 4 + 3];
        float p = red_pos[tid * 4 + 0] + red_pos[tid * 4 + 1]
                + red_pos[tid * 4 + 2] + red_pos[tid * 4 + 3];
        scratch[PR_ALL + (size_t)q * N_TOT + i0 + tid] = a;
        scratch[PR_POS + (size_t)q * N_TOT + i0 + tid] = p;
    }
    #pragma unroll
    for (int s = 0; s < 8; s++) { sall[s] = 0.f; spos[s] = 0.f; }
}

// ============================================================================
// Kernel 2: symmetric (upper-triangle) HMMA gram.
// Pair p handles row tiles {p, 63-p}: 65 tiles in two contiguous runs,
// split over 4 CTAs (chunks q). 128 CTAs total, 256 threads.
// ============================================================================
__global__ void __launch_bounds__(256, 1) milnce_mma_kernel() {
    extern __shared__ char smem[];
    const uint32_t sb = smem_u32(smem);

    const int tid  = threadIdx.x;
    const int wid  = tid >> 5;
    const int lane = tid & 31;
    const int wm   = wid >> 2;
    const int wn   = wid & 3;
    const int p    = blockIdx.x >> 2;
    const int q    = blockIdx.x & 3;

    const int L0      = NROWT - p;                 // length of row-run p
    const int u_begin = (q * 65) >> 2;
    const int u_end   = ((q + 1) * 65) >> 2;

    const int lrow16 = (lane & 7) + ((lane >> 3) & 1) * 8;
    const int lkb    = (lane >> 4) * 16;
    const uint32_t a_lane = sb + A_OFF + (uint32_t)((wm * 64 + lrow16) * ROW_BYTES + lkb);
    const uint32_t b_off  = (uint32_t)((wn * 32 + lrow16) * ROW_BYTES + lkb);

    int it = (u_begin < L0) ? p : (63 - p);
    int i0 = it * TILE_M;

    // jt for a given u
    auto tile_jt = [&](int u) { return (u < L0) ? (p + u) : (63 - p) + (u - L0); };

    // prologue: A + B(u_begin) (group 0), B(u_begin+1) (group 1)
    issue_tile(sb + A_OFF, i0, tid);
    issue_tile(sb + B0_OFF, tile_jt(u_begin) * TILE_M, tid);
    CP_COMMIT();
    issue_tile(sb + B1_OFF, tile_jt(u_begin + 1) * TILE_M, tid);
    CP_COMMIT();

    int labr[8];
    #pragma unroll
    for (int s = 0; s < 8; s++)
        labr[s] = lab_buf[i0 + wm * 64 + (s >> 1) * 16 + (s & 1) * 8 + (lane >> 2)];

    float sall[8] = {0,0,0,0,0,0,0,0};
    float spos[8] = {0,0,0,0,0,0,0,0};
    float acc[4][4][4];

    #pragma unroll 1
    for (int u = u_begin; u < u_end; u++) {
        const int rel = u - u_begin;
        const int jt  = tile_jt(u);
        const uint32_t b_lane = sb + ((rel & 1) ? B1_OFF : B0_OFF) + b_off;

        if (u == L0 && u != u_begin) {
            // row change: flush old row block, reload A
            flush_rows(smem, sall, spos, i0, q, wm, wn, lane, tid);
            it = 63 - p;
            i0 = it * TILE_M;
            #pragma unroll
            for (int s = 0; s < 8; s++)
                labr[s] = lab_buf[i0 + wm * 64 + (s >> 1) * 16 + (s & 1) * 8 + (lane >> 2)];
            CP_WAIT(0);
            __syncthreads();
            issue_tile(sb + A_OFF, i0, tid);
            CP_COMMIT();
            CP_WAIT(0);
            __syncthreads();
        } else {
            if (u == u_end - 1) { CP_WAIT(0); } else { CP_WAIT(1); }
            __syncthreads();
        }

        mma_tile(acc, a_lane, b_lane);

        __syncthreads();   // all warps done reading this B buffer
        if (u + 2 < u_end) {
            issue_tile(sb + ((rel & 1) ? B1_OFF : B0_OFF), tile_jt(u + 2) * TILE_M, tid);
            CP_COMMIT();
        }

        if (jt == it) epilogue<true >(acc, i0, it, jt, wm, wn, lane, labr, sall, spos);
        else          epilogue<false>(acc, i0, it, jt, wm, wn, lane, labr, sall, spos);
    }

    flush_rows(smem, sall, spos, i0, q, wm, wn, lane, tid);
}

// ============================================================================
// Kernel 3a: per-row loss from partials.  Kernel 3b: total.
// ============================================================================
__global__ void finalize1_kernel() {
    int i = blockIdx.x * blockDim.x + threadIdx.x;
    float a = 0.f, p = 0.f;
    #pragma unroll
    for (int s = 0; s < 4; s++) {
        a += scratch[PR_ALL + (size_t)s * N_TOT + i];
        p += scratch[PR_POS + (size_t)s * N_TOT + i];
    }
    #pragma unroll 4
    for (int s = 0; s < 128; s++) {
        a += scratch[PC_ALL + (size_t)s * N_TOT + i];
        p += scratch[PC_POS + (size_t)s * N_TOT + i];
    }
    rowloss[i] = logf(a) - logf(p);
}

__global__ void finalize2_kernel(float* __restrict__ out) {
    __shared__ float red[256];
    float s = 0.f;
    for (int i = threadIdx.x; i < N_TOT; i += 256) s += rowloss[i];
    red[threadIdx.x] = s;
    __syncthreads();
    for (int o = 128; o > 0; o >>= 1) {
        if (threadIdx.x < o) red[threadIdx.x] += red[threadIdx.x + o];
        __syncthreads();
    }
    if (threadIdx.x == 0) out[0] = red[0];
}

// ============================================================================
extern "C" void kernel_launch(void* const* d_in, const int* in_sizes, int n_in,
                              void* d_out, int out_size) {
    const float* feats  = (const float*)d_in[0];
    const float* posf   = (const float*)d_in[1];
    const int*   labels = (const int*)d_in[2];

    prep_kernel<<<N_TOT / 8, 256>>>(feats, posf, labels);

    cudaFuncSetAttribute(milnce_mma_kernel,
                         cudaFuncAttributeMaxDynamicSharedMemorySize, SMEM_TOTAL);
    milnce_mma_kernel<<<128, 256, SMEM_TOTAL>>>();

    finalize1_kernel<<<N_TOT / 256, 256>>>();
    finalize2_kernel<<<1, 256>>>((float*)d_out);
}

// round 8
// speedup vs baseline: 3.1606x; 1.0523x over previous
#include <cuda_runtime.h>
#include <cuda_bf16.h>
#include <cstdint>

#define N_TOT   8192
#define D_DIM   256
#define B_HALF  4096
#define TILE_M  128
#define NROWT   64                 // 128-row tiles
#define K_STEPS 16                 // 256 / 16

#define ROW_BYTES 528              // 264 bf16 row pitch (bank-conflict-free ldmatrix)
#define A_OFF   0
#define B0_OFF  (TILE_M * ROW_BYTES)                 // 67584
#define B1_OFF  (B0_OFF + TILE_M * ROW_BYTES)        // 135168
#define RED_OFF (B1_OFF + TILE_M * ROW_BYTES)        // 202752
#define SMEM_TOTAL (RED_OFF + 128 * 4 * 2 * 4)       // 206848

// -------- device scratch --------
__device__ __align__(16) __nv_bfloat16 g_bf[N_TOT * D_DIM];   // normalized bf16 (4 MB)
__device__ int   lab_buf[N_TOT];

// partial-sum scratch:
//   part_row_all[4][8192], part_row_pos[4][8192]      (chunk slots; zeroed in prep)
//   part_col_all[128][8192], part_col_pos[128][8192]  (slot = it*2+wm; NOT zeroed --
//       for column tile jt exactly slots [0, 2*jt) are written each launch, and the
//       finalize kernel reads only those)
#define PR_ALL  0
#define PR_POS  (4 * N_TOT)
#define PC_ALL  (8 * N_TOT)
#define PC_POS  (PC_ALL + 128 * N_TOT)
#define SCRATCH_FLOATS (PC_POS + 128 * N_TOT)
__device__ __align__(16) float scratch[SCRATCH_FLOATS];
__device__ float blocksum[64];
__device__ unsigned int fin_counter = 0;   // self-resetting via wrapping atomicInc

// ======================= helpers =======================
static __device__ __forceinline__ uint32_t smem_u32(const void* p) {
    uint32_t a;
    asm("{ .reg .u64 t; cvta.to.shared.u64 t, %1; cvt.u32.u64 %0, t; }" : "=r"(a) : "l"(p));
    return a;
}
static __device__ __forceinline__ float ex2f(float x) {
    float r; asm("ex2.approx.ftz.f32 %0, %1;" : "=f"(r) : "f"(x)); return r;
}
static __device__ __forceinline__ uint32_t pack_bf2(float lo, float hi) {
    uint32_t r; asm("cvt.rn.bf16x2.f32 %0, %1, %2;" : "=r"(r) : "f"(hi), "f"(lo)); return r;
}
static __device__ __forceinline__ void cp16(uint32_t saddr, const void* g) {
    asm volatile("cp.async.cg.shared.global [%0], [%1], 16;" :: "r"(saddr), "l"(g) : "memory");
}
#define CP_COMMIT() asm volatile("cp.async.commit_group;" ::: "memory")
#define CP_WAIT(n)  asm volatile("cp.async.wait_group %0;" :: "n"(n) : "memory")

static __device__ __forceinline__ void ldsm_x4(uint32_t& r0, uint32_t& r1,
                                               uint32_t& r2, uint32_t& r3, uint32_t a) {
    asm volatile("ldmatrix.sync.aligned.m8n8.x4.shared.b16 {%0,%1,%2,%3}, [%4];"
                 : "=r"(r0), "=r"(r1), "=r"(r2), "=r"(r3) : "r"(a));
}
static __device__ __forceinline__ void mma16816(float* d, const uint32_t* a,
                                                uint32_t b0, uint32_t b1) {
    asm volatile(
        "mma.sync.aligned.m16n8k16.row.col.f32.bf16.bf16.f32 "
        "{%0,%1,%2,%3}, {%4,%5,%6,%7}, {%8,%9}, {%0,%1,%2,%3};"
        : "+f"(d[0]), "+f"(d[1]), "+f"(d[2]), "+f"(d[3])
        : "r"(a[0]), "r"(a[1]), "r"(a[2]), "r"(a[3]), "r"(b0), "r"(b1));
}

// ============================================================================
// Kernel 1: normalize rows -> bf16, labels; zero ONLY the row-slot scratch.
// ============================================================================
__global__ void prep_kernel(const float* __restrict__ feats,
                            const float* __restrict__ posf,
                            const int* __restrict__ labels) {
    int row  = blockIdx.x * 8 + (threadIdx.x >> 5);
    int lane = threadIdx.x & 31;
    const float* src = (row < B_HALF) ? (feats + (size_t)row * D_DIM)
                                      : (posf + (size_t)(row - B_HALF) * D_DIM);
    const float4* s4 = reinterpret_cast<const float4*>(src);
    float4 v0 = s4[lane];
    float4 v1 = s4[lane + 32];
    float ss = v0.x*v0.x + v0.y*v0.y + v0.z*v0.z + v0.w*v0.w
             + v1.x*v1.x + v1.y*v1.y + v1.z*v1.z + v1.w*v1.w;
    #pragma unroll
    for (int off = 16; off > 0; off >>= 1)
        ss += __shfl_xor_sync(0xffffffffu, ss, off);
    float inv = rsqrtf(ss);
    uint2 o0, o1;
    o0.x = pack_bf2(v0.x * inv, v0.y * inv);
    o0.y = pack_bf2(v0.z * inv, v0.w * inv);
    o1.x = pack_bf2(v1.x * inv, v1.y * inv);
    o1.y = pack_bf2(v1.z * inv, v1.w * inv);
    uint2* dst = reinterpret_cast<uint2*>(g_bf + (size_t)row * D_DIM);
    dst[lane]      = o0;
    dst[lane + 32] = o1;
    if (lane == 0)
        lab_buf[row] = labels[(row < B_HALF) ? row : row - B_HALF];

    // zero the 8*N_TOT row-slot floats (64K floats = 16K float4)
    int gidx = blockIdx.x * blockDim.x + threadIdx.x;
    if (gidx < (8 * N_TOT) / 4)
        reinterpret_cast<float4*>(scratch)[gidx] = make_float4(0.f, 0.f, 0.f, 0.f);
}

// issue async copy of one 128x256 bf16 tile into smem (row stride 528B)
static __device__ __forceinline__ void issue_tile(uint32_t sbuf, int row0, int tid) {
    const uint4* src = reinterpret_cast<const uint4*>(g_bf);
    #pragma unroll
    for (int t = 0; t < 16; t++) {
        int id = tid + t * 256;
        int r  = id >> 5;
        int kc = id & 31;
        cp16(sbuf + r * ROW_BYTES + kc * 16, src + (size_t)(row0 + r) * 32 + kc);
    }
}

// ============================================================================
// MMA for one 128x128 tile (zeroed acc).
// ============================================================================
static __device__ __forceinline__ void mma_tile(float (&acc)[4][4][4],
                                                uint32_t a_lane, uint32_t b_lane) {
    #pragma unroll
    for (int ms = 0; ms < 4; ms++)
        #pragma unroll
        for (int ns = 0; ns < 4; ns++)
            #pragma unroll
            for (int c = 0; c < 4; c++) acc[ms][ns][c] = 0.f;

    #pragma unroll 2
    for (int ks = 0; ks < K_STEPS; ks++) {
        const uint32_t koff = (uint32_t)(ks * 32);
        uint32_t a[4][4];
        #pragma unroll
        for (int ms = 0; ms < 4; ms++)
            ldsm_x4(a[ms][0], a[ms][1], a[ms][2], a[ms][3],
                    a_lane + (uint32_t)(ms * 16 * ROW_BYTES) + koff);
        uint32_t b[2][4];
        #pragma unroll
        for (int p = 0; p < 2; p++)
            ldsm_x4(b[p][0], b[p][1], b[p][2], b[p][3],
                    b_lane + (uint32_t)(p * 16 * ROW_BYTES) + koff);
        #pragma unroll
        for (int ms = 0; ms < 4; ms++) {
            mma16816(acc[ms][0], a[ms], b[0][0], b[0][2]);
            mma16816(acc[ms][1], a[ms], b[0][1], b[0][3]);
            mma16816(acc[ms][2], a[ms], b[1][0], b[1][2]);
            mma16816(acc[ms][3], a[ms], b[1][1], b[1][3]);
        }
    }
}

// ============================================================================
// Epilogue. DIAG: diagonal tile (mask i==j, row sums only).
// Off-diag: row sums + column sums (written to part_col slot it*2+wm).
// ============================================================================
template <bool DIAG>
static __device__ __forceinline__ void epilogue(const float (&acc)[4][4][4],
        int i0, int it, int jt, int wm, int wn, int lane,
        const int (&labr)[8], float (&sall)[8], float (&spos)[8]) {
    const float K_EXP = 14.42695040888963f;   // log2(e)/tau
    const int jbase = jt * TILE_M;
    int labc[4][2];
    #pragma unroll
    for (int ns = 0; ns < 4; ns++) {
        int c0 = jbase + wn * 32 + ns * 8 + (lane & 3) * 2;
        labc[ns][0] = lab_buf[c0];
        labc[ns][1] = lab_buf[c0 + 1];
    }
    float ecall[8], ecpos[8];
    #pragma unroll
    for (int x = 0; x < 8; x++) { ecall[x] = 0.f; ecpos[x] = 0.f; }

    #pragma unroll
    for (int ms = 0; ms < 4; ms++) {
        const int gi_lo = i0 + wm * 64 + ms * 16 + (lane >> 2);
        #pragma unroll
        for (int ns = 0; ns < 4; ns++) {
            const int gj0 = jbase + wn * 32 + ns * 8 + (lane & 3) * 2;
            #pragma unroll
            for (int c = 0; c < 4; c++) {
                const int rh   = c >> 1;
                const int slot = ms * 2 + rh;
                const int b    = c & 1;
                float e = ex2f(acc[ms][ns][c] * K_EXP);
                bool match = (labc[ns][b] == labr[slot]);
                if (DIAG) {
                    if ((gi_lo + rh * 8) != (gj0 + b)) {
                        sall[slot] += e;
                        if (match) spos[slot] += e;
                    }
                } else {
                    sall[slot] += e;
                    ecall[ns * 2 + b] += e;
                    if (match) { spos[slot] += e; ecpos[ns * 2 + b] += e; }
                }
            }
        }
    }

    if (!DIAG) {
        #pragma unroll
        for (int x = 0; x < 8; x++) {
            #pragma unroll
            for (int off = 4; off < 32; off <<= 1) {
                ecall[x] += __shfl_xor_sync(0xffffffffu, ecall[x], off);
                ecpos[x] += __shfl_xor_sync(0xffffffffu, ecpos[x], off);
            }
        }
        if (lane < 4) {
            const int slot = it * 2 + wm;
            float2* pa = reinterpret_cast<float2*>(scratch + PC_ALL + (size_t)slot * N_TOT);
            float2* pp = reinterpret_cast<float2*>(scratch + PC_POS + (size_t)slot * N_TOT);
            #pragma unroll
            for (int ns = 0; ns < 4; ns++) {
                int cidx = (jbase + wn * 32 + ns * 8 + lane * 2) >> 1;
                pa[cidx] = make_float2(ecall[ns * 2], ecall[ns * 2 + 1]);
                pp[cidx] = make_float2(ecpos[ns * 2], ecpos[ns * 2 + 1]);
            }
        }
    }
}

// flush accumulated row sums for the current row block into part_row slot q
static __device__ __forceinline__ void flush_rows(char* smem, float (&sall)[8],
        float (&spos)[8], int i0, int q, int wm, int wn, int lane, int tid) {
    #pragma unroll
    for (int s = 0; s < 8; s++) {
        sall[s] += __shfl_xor_sync(0xffffffffu, sall[s], 1);
        sall[s] += __shfl_xor_sync(0xffffffffu, sall[s], 2);
        spos[s] += __shfl_xor_sync(0xffffffffu, spos[s], 1);
        spos[s] += __shfl_xor_sync(0xffffffffu, spos[s], 2);
    }
    float* red_all = reinterpret_cast<float*>(smem + RED_OFF);   // [128][4]
    float* red_pos = red_all + 128 * 4;
    __syncthreads();
    if ((lane & 3) == 0) {
        #pragma unroll
        for (int s = 0; s < 8; s++) {
            int rloc = wm * 64 + (s >> 1) * 16 + (s & 1) * 8 + (lane >> 2);
            red_all[rloc * 4 + wn] = sall[s];
            red_pos[rloc * 4 + wn] = spos[s];
        }
    }
    __syncthreads();
    if (tid < 128) {
        float a = red_all[tid * 4 + 0] + red_all[tid * 4 + 1]
                + red_all[tid * 4 + 2] + red_all[tid * 4 + 3];
        float p = red_pos[tid * 4 + 0] + red_pos[tid * 4 + 1]
                + red_pos[tid * 4 + 2] + red_pos[tid * 4 + 3];
        scratch[PR_ALL + (size_t)q * N_TOT + i0 + tid] = a;
        scratch[PR_POS + (size_t)q * N_TOT + i0 + tid] = p;
    }
    #pragma unroll
    for (int s = 0; s < 8; s++) { sall[s] = 0.f; spos[s] = 0.f; }
}

// ============================================================================
// Kernel 2: symmetric (upper-triangle) HMMA gram.
// Pair p handles row tiles {p, 63-p}: 65 tiles, split over 4 CTAs.
// ============================================================================
__global__ void __launch_bounds__(256, 1) milnce_mma_kernel() {
    extern __shared__ char smem[];
    const uint32_t sb = smem_u32(smem);

    const int tid  = threadIdx.x;
    const int wid  = tid >> 5;
    const int lane = tid & 31;
    const int wm   = wid >> 2;
    const int wn   = wid & 3;
    const int p    = blockIdx.x >> 2;
    const int q    = blockIdx.x & 3;

    const int L0      = NROWT - p;
    const int u_begin = (q * 65) >> 2;
    const int u_end   = ((q + 1) * 65) >> 2;

    const int lrow16 = (lane & 7) + ((lane >> 3) & 1) * 8;
    const int lkb    = (lane >> 4) * 16;
    const uint32_t a_lane = sb + A_OFF + (uint32_t)((wm * 64 + lrow16) * ROW_BYTES + lkb);
    const uint32_t b_off  = (uint32_t)((wn * 32 + lrow16) * ROW_BYTES + lkb);

    int it = (u_begin < L0) ? p : (63 - p);
    int i0 = it * TILE_M;

    auto tile_jt = [&](int u) { return (u < L0) ? (p + u) : (63 - p) + (u - L0); };

    issue_tile(sb + A_OFF, i0, tid);
    issue_tile(sb + B0_OFF, tile_jt(u_begin) * TILE_M, tid);
    CP_COMMIT();
    issue_tile(sb + B1_OFF, tile_jt(u_begin + 1) * TILE_M, tid);
    CP_COMMIT();

    int labr[8];
    #pragma unroll
    for (int s = 0; s < 8; s++)
        labr[s] = lab_buf[i0 + wm * 64 + (s >> 1) * 16 + (s & 1) * 8 + (lane >> 2)];

    float sall[8] = {0,0,0,0,0,0,0,0};
    float spos[8] = {0,0,0,0,0,0,0,0};
    float acc[4][4][4];

    #pragma unroll 1
    for (int u = u_begin; u < u_end; u++) {
        const int rel = u - u_begin;
        const int jt  = tile_jt(u);
        const uint32_t b_lane = sb + ((rel & 1) ? B1_OFF : B0_OFF) + b_off;

        if (u == L0 && u != u_begin) {
            flush_rows(smem, sall, spos, i0, q, wm, wn, lane, tid);
            it = 63 - p;
            i0 = it * TILE_M;
            #pragma unroll
            for (int s = 0; s < 8; s++)
                labr[s] = lab_buf[i0 + wm * 64 + (s >> 1) * 16 + (s & 1) * 8 + (lane >> 2)];
            CP_WAIT(0);
            __syncthreads();
            issue_tile(sb + A_OFF, i0, tid);
            CP_COMMIT();
            CP_WAIT(0);
            __syncthreads();
        } else {
            if (u == u_end - 1) { CP_WAIT(0); } else { CP_WAIT(1); }
            __syncthreads();
        }

        mma_tile(acc, a_lane, b_lane);

        __syncthreads();
        if (u + 2 < u_end) {
            issue_tile(sb + ((rel & 1) ? B1_OFF : B0_OFF), tile_jt(u + 2) * TILE_M, tid);
            CP_COMMIT();
        }

        if (jt == it) epilogue<true >(acc, i0, it, jt, wm, wn, lane, labr, sall, spos);
        else          epilogue<false>(acc, i0, it, jt, wm, wn, lane, labr, sall, spos);
    }

    flush_rows(smem, sall, spos, i0, q, wm, wn, lane, tid);
}

// ============================================================================
// Kernel 3 (fused): per-row loss + block partial + last-block total.
// Grid = 64 blocks x 128 threads; block blk covers column tile jt = blk,
// so only slots [0, 2*jt) of the col scratch are read (rest never written).
// ============================================================================
__global__ void finalize_kernel(float* __restrict__ out) {
    __shared__ float red[128];
    __shared__ bool  is_last;
    const int blk = blockIdx.x;
    const int i   = blk * 128 + threadIdx.x;
    const int jt  = blk;

    float a0 = 0.f, p0 = 0.f, a1 = 0.f, p1 = 0.f;
    #pragma unroll
    for (int s = 0; s < 4; s++) {
        a0 += scratch[PR_ALL + (size_t)s * N_TOT + i];
        p0 += scratch[PR_POS + (size_t)s * N_TOT + i];
    }
    const int nslots = 2 * jt;
    #pragma unroll 4
    for (int s = 0; s < nslots; s++) {
        if (s & 1) {
            a1 += scratch[PC_ALL + (size_t)s * N_TOT + i];
            p1 += scratch[PC_POS + (size_t)s * N_TOT + i];
        } else {
            a0 += scratch[PC_ALL + (size_t)s * N_TOT + i];
            p0 += scratch[PC_POS + (size_t)s * N_TOT + i];
        }
    }
    float a = a0 + a1, p = p0 + p1;
    red[threadIdx.x] = logf(a) - logf(p);
    __syncthreads();
    #pragma unroll
    for (int o = 64; o > 0; o >>= 1) {
        if (threadIdx.x < o) red[threadIdx.x] += red[threadIdx.x + o];
        __syncthreads();
    }
    if (threadIdx.x == 0) {
        blocksum[blk] = red[0];
        __threadfence();
        unsigned int t = atomicInc(&fin_counter, 63);   // wraps to 0 -> self-resets
        is_last = (t == 63);
    }
    __syncthreads();
    if (is_last) {
        float s = (threadIdx.x < 64) ? blocksum[threadIdx.x] : 0.f;
        red[threadIdx.x] = s;
        __syncthreads();
        #pragma unroll
        for (int o = 64; o > 0; o >>= 1) {
            if (threadIdx.x < o) red[threadIdx.x] += red[threadIdx.x + o];
            __syncthreads();
        }
        if (threadIdx.x == 0) out[0] = red[0];
    }
}

// ============================================================================
extern "C" void kernel_launch(void* const* d_in, const int* in_sizes, int n_in,
                              void* d_out, int out_size) {
    const float* feats  = (const float*)d_in[0];
    const float* posf   = (const float*)d_in[1];
    const int*   labels = (const int*)d_in[2];

    prep_kernel<<<N_TOT / 8, 256>>>(feats, posf, labels);

    cudaFuncSetAttribute(milnce_mma_kernel,
                         cudaFuncAttributeMaxDynamicSharedMemorySize, SMEM_TOTAL);
    milnce_mma_kernel<<<128, 256, SMEM_TOTAL>>>();

    finalize_kernel<<<64, 128>>>((float*)d_out);
}

// round 9
// speedup vs baseline: 3.3952x; 1.0742x over previous
#include <cuda_runtime.h>
#include <cuda_bf16.h>
#include <cstdint>

#define N_TOT   8192
#define D_DIM   256
#define TILE_M  128
#define B_HALF  4096
#define NROWT   64
#define K_STEPS 16
#define NTILES  2080               // 64*65/2 upper-triangle tiles
#define NCTA    148

#define ROW_BYTES 528
#define A_OFF   0
#define B0_OFF  (TILE_M * ROW_BYTES)
#define B1_OFF  (B0_OFF + TILE_M * ROW_BYTES)
#define RED_OFF (B1_OFF + TILE_M * ROW_BYTES)
#define SMEM_TOTAL (RED_OFF + 128 * 4 * 2 * 4)

// -------- device scratch --------
__device__ __align__(16) __nv_bfloat16 g_bf[N_TOT * D_DIM];
__device__ int   lab_buf[N_TOT];

// part_row[8][8192] x2 (zeroed), part_col[128][8192] x2 (written-only-where-read)
#define PR_ALL  0
#define PR_POS  (8 * N_TOT)
#define PC_ALL  (16 * N_TOT)
#define PC_POS  (PC_ALL + 128 * N_TOT)
#define SCRATCH_FLOATS (PC_POS + 128 * N_TOT)
__device__ __align__(16) float scratch[SCRATCH_FLOATS];
__device__ float blocksum[64];
__device__ unsigned int fin_counter = 0;

// ======================= helpers =======================
static __device__ __forceinline__ uint32_t smem_u32(const void* p) {
    uint32_t a;
    asm("{ .reg .u64 t; cvta.to.shared.u64 t, %1; cvt.u32.u64 %0, t; }" : "=r"(a) : "l"(p));
    return a;
}
static __device__ __forceinline__ float ex2f(float x) {
    float r; asm("ex2.approx.ftz.f32 %0, %1;" : "=f"(r) : "f"(x)); return r;
}
static __device__ __forceinline__ uint32_t pack_bf2(float lo, float hi) {
    uint32_t r; asm("cvt.rn.bf16x2.f32 %0, %1, %2;" : "=r"(r) : "f"(hi), "f"(lo)); return r;
}
static __device__ __forceinline__ void cp16(uint32_t saddr, const void* g) {
    asm volatile("cp.async.cg.shared.global [%0], [%1], 16;" :: "r"(saddr), "l"(g) : "memory");
}
#define CP_COMMIT() asm volatile("cp.async.commit_group;" ::: "memory")
#define CP_WAIT(n)  asm volatile("cp.async.wait_group %0;" :: "n"(n) : "memory")

static __device__ __forceinline__ void ldsm_x4(uint32_t& r0, uint32_t& r1,
                                               uint32_t& r2, uint32_t& r3, uint32_t a) {
    asm volatile("ldmatrix.sync.aligned.m8n8.x4.shared.b16 {%0,%1,%2,%3}, [%4];"
                 : "=r"(r0), "=r"(r1), "=r"(r2), "=r"(r3) : "r"(a));
}
static __device__ __forceinline__ void mma16816(float* d, const uint32_t* a,
                                                uint32_t b0, uint32_t b1) {
    asm volatile(
        "mma.sync.aligned.m16n8k16.row.col.f32.bf16.bf16.f32 "
        "{%0,%1,%2,%3}, {%4,%5,%6,%7}, {%8,%9}, {%0,%1,%2,%3};"
        : "+f"(d[0]), "+f"(d[1]), "+f"(d[2]), "+f"(d[3])
        : "r"(a[0]), "r"(a[1]), "r"(a[2]), "r"(a[3]), "r"(b0), "r"(b1));
}

// ---- schedule mapping (pair order: [64][1][63][2]...[33][32]) ----
static __device__ __forceinline__ void map_u(int u, int& it, int& jt) {
    int p = u / 65, off = u - p * 65;
    int l0 = 64 - p;
    if (off < l0) { it = p;      jt = p + off; }
    else          { it = 63 - p; jt = (63 - p) + (off - l0); }
}
static __device__ __forceinline__ int map_jt(int u) {
    int it, jt; map_u(u, it, jt); return jt;
}
static __device__ __forceinline__ int chunk_of(int u) {
    return (u < 120) ? (u / 15) : (8 + (u - 120) / 14);
}
static __device__ __forceinline__ int strip_start(int it) {
    int p = (it < 32) ? it : 63 - it;
    return (it < 32) ? (65 * p) : (65 * p + (64 - p));
}

// ============================================================================
// Kernel 1: normalize -> bf16, labels, zero the 8-slot row scratch.
// ============================================================================
__global__ void prep_kernel(const float* __restrict__ feats,
                            const float* __restrict__ posf,
                            const int* __restrict__ labels) {
    int row  = blockIdx.x * 8 + (threadIdx.x >> 5);
    int lane = threadIdx.x & 31;
    const float* src = (row < B_HALF) ? (feats + (size_t)row * D_DIM)
                                      : (posf + (size_t)(row - B_HALF) * D_DIM);
    const float4* s4 = reinterpret_cast<const float4*>(src);
    float4 v0 = s4[lane];
    float4 v1 = s4[lane + 32];
    float ss = v0.x*v0.x + v0.y*v0.y + v0.z*v0.z + v0.w*v0.w
             + v1.x*v1.x + v1.y*v1.y + v1.z*v1.z + v1.w*v1.w;
    #pragma unroll
    for (int off = 16; off > 0; off >>= 1)
        ss += __shfl_xor_sync(0xffffffffu, ss, off);
    float inv = rsqrtf(ss);
    uint2 o0, o1;
    o0.x = pack_bf2(v0.x * inv, v0.y * inv);
    o0.y = pack_bf2(v0.z * inv, v0.w * inv);
    o1.x = pack_bf2(v1.x * inv, v1.y * inv);
    o1.y = pack_bf2(v1.z * inv, v1.w * inv);
    uint2* dst = reinterpret_cast<uint2*>(g_bf + (size_t)row * D_DIM);
    dst[lane]      = o0;
    dst[lane + 32] = o1;
    if (lane == 0)
        lab_buf[row] = labels[(row < B_HALF) ? row : row - B_HALF];

    int gidx = blockIdx.x * blockDim.x + threadIdx.x;
    if (gidx < (16 * N_TOT) / 4)
        reinterpret_cast<float4*>(scratch)[gidx] = make_float4(0.f, 0.f, 0.f, 0.f);
}

static __device__ __forceinline__ void issue_tile(uint32_t sbuf, int row0, int tid) {
    const uint4* src = reinterpret_cast<const uint4*>(g_bf);
    #pragma unroll
    for (int t = 0; t < 16; t++) {
        int id = tid + t * 256;
        int r  = id >> 5;
        int kc = id & 31;
        cp16(sbuf + r * ROW_BYTES + kc * 16, src + (size_t)(row0 + r) * 32 + kc);
    }
}

static __device__ __forceinline__ void mma_tile(float (&acc)[4][4][4],
                                                uint32_t a_lane, uint32_t b_lane) {
    #pragma unroll
    for (int ms = 0; ms < 4; ms++)
        #pragma unroll
        for (int ns = 0; ns < 4; ns++)
            #pragma unroll
            for (int c = 0; c < 4; c++) acc[ms][ns][c] = 0.f;

    #pragma unroll 2
    for (int ks = 0; ks < K_STEPS; ks++) {
        const uint32_t koff = (uint32_t)(ks * 32);
        uint32_t a[4][4];
        #pragma unroll
        for (int ms = 0; ms < 4; ms++)
            ldsm_x4(a[ms][0], a[ms][1], a[ms][2], a[ms][3],
                    a_lane + (uint32_t)(ms * 16 * ROW_BYTES) + koff);
        uint32_t b[2][4];
        #pragma unroll
        for (int p = 0; p < 2; p++)
            ldsm_x4(b[p][0], b[p][1], b[p][2], b[p][3],
                    b_lane + (uint32_t)(p * 16 * ROW_BYTES) + koff);
        #pragma unroll
        for (int ms = 0; ms < 4; ms++) {
            mma16816(acc[ms][0], a[ms], b[0][0], b[0][2]);
            mma16816(acc[ms][1], a[ms], b[0][1], b[0][3]);
            mma16816(acc[ms][2], a[ms], b[1][0], b[1][2]);
            mma16816(acc[ms][3], a[ms], b[1][1], b[1][3]);
        }
    }
}

template <bool DIAG>
static __device__ __forceinline__ void epilogue(const float (&acc)[4][4][4],
        int i0, int it, int jt, int wm, int wn, int lane,
        const int (&labr)[8], float (&sall)[8], float (&spos)[8]) {
    const float K_EXP = 14.42695040888963f;
    const int jbase = jt * TILE_M;
    int labc[4][2];
    #pragma unroll
    for (int ns = 0; ns < 4; ns++) {
        int c0 = jbase + wn * 32 + ns * 8 + (lane & 3) * 2;
        labc[ns][0] = lab_buf[c0];
        labc[ns][1] = lab_buf[c0 + 1];
    }
    float ecall[8], ecpos[8];
    #pragma unroll
    for (int x = 0; x < 8; x++) { ecall[x] = 0.f; ecpos[x] = 0.f; }

    #pragma unroll
    for (int ms = 0; ms < 4; ms++) {
        const int gi_lo = i0 + wm * 64 + ms * 16 + (lane >> 2);
        #pragma unroll
        for (int ns = 0; ns < 4; ns++) {
            const int gj0 = jbase + wn * 32 + ns * 8 + (lane & 3) * 2;
            #pragma unroll
            for (int c = 0; c < 4; c++) {
                const int rh   = c >> 1;
                const int slot = ms * 2 + rh;
                const int b    = c & 1;
                float e = ex2f(acc[ms][ns][c] * K_EXP);
                bool match = (labc[ns][b] == labr[slot]);
                if (DIAG) {
                    if ((gi_lo + rh * 8) != (gj0 + b)) {
                        sall[slot] += e;
                        if (match) spos[slot] += e;
                    }
                } else {
                    sall[slot] += e;
                    ecall[ns * 2 + b] += e;
                    if (match) { spos[slot] += e; ecpos[ns * 2 + b] += e; }
                }
            }
        }
    }

    if (!DIAG) {
        #pragma unroll
        for (int x = 0; x < 8; x++) {
            #pragma unroll
            for (int off = 4; off < 32; off <<= 1) {
                ecall[x] += __shfl_xor_sync(0xffffffffu, ecall[x], off);
                ecpos[x] += __shfl_xor_sync(0xffffffffu, ecpos[x], off);
            }
        }
        if (lane < 4) {
            const int slot = it * 2 + wm;
            float2* pa = reinterpret_cast<float2*>(scratch + PC_ALL + (size_t)slot * N_TOT);
            float2* pp = reinterpret_cast<float2*>(scratch + PC_POS + (size_t)slot * N_TOT);
            #pragma unroll
            for (int ns = 0; ns < 4; ns++) {
                int cidx = (jbase + wn * 32 + ns * 8 + lane * 2) >> 1;
                pa[cidx] = make_float2(ecall[ns * 2], ecall[ns * 2 + 1]);
                pp[cidx] = make_float2(ecpos[ns * 2], ecpos[ns * 2 + 1]);
            }
        }
    }
}

static __device__ __forceinline__ void flush_rows(char* smem, float (&sall)[8],
        float (&spos)[8], int i0, int rslot, int wm, int wn, int lane, int tid) {
    #pragma unroll
    for (int s = 0; s < 8; s++) {
        sall[s] += __shfl_xor_sync(0xffffffffu, sall[s], 1);
        sall[s] += __shfl_xor_sync(0xffffffffu, sall[s], 2);
        spos[s] += __shfl_xor_sync(0xffffffffu, spos[s], 1);
        spos[s] += __shfl_xor_sync(0xffffffffu, spos[s], 2);
    }
    float* red_all = reinterpret_cast<float*>(smem + RED_OFF);
    float* red_pos = red_all + 128 * 4;
    __syncthreads();
    if ((lane & 3) == 0) {
        #pragma unroll
        for (int s = 0; s < 8; s++) {
            int rloc = wm * 64 + (s >> 1) * 16 + (s & 1) * 8 + (lane >> 2);
            red_all[rloc * 4 + wn] = sall[s];
            red_pos[rloc * 4 + wn] = spos[s];
        }
    }
    __syncthreads();
    if (tid < 128) {
        float a = red_all[tid * 4 + 0] + red_all[tid * 4 + 1]
                + red_all[tid * 4 + 2] + red_all[tid * 4 + 3];
        float p = red_pos[tid * 4 + 0] + red_pos[tid * 4 + 1]
                + red_pos[tid * 4 + 2] + red_pos[tid * 4 + 3];
        scratch[PR_ALL + (size_t)rslot * N_TOT + i0 + tid] = a;
        scratch[PR_POS + (size_t)rslot * N_TOT + i0 + tid] = p;
    }
    #pragma unroll
    for (int s = 0; s < 8; s++) { sall[s] = 0.f; spos[s] = 0.f; }
}

// ============================================================================
// Kernel 2: balanced 148-CTA symmetric HMMA gram.
// CTA c handles contiguous tiles [t0, t1) of the pair-ordered sequence.
// ============================================================================
__global__ void __launch_bounds__(256, 1) milnce_mma_kernel() {
    extern __shared__ char smem[];
    const uint32_t sb = smem_u32(smem);

    const int tid  = threadIdx.x;
    const int wid  = tid >> 5;
    const int lane = tid & 31;
    const int wm   = wid >> 2;
    const int wn   = wid & 3;
    const int c    = blockIdx.x;

    const int t0 = (c < 8) ? c * 15 : 120 + (c - 8) * 14;
    const int t1 = t0 + ((c < 8) ? 15 : 14);

    const int lrow16 = (lane & 7) + ((lane >> 3) & 1) * 8;
    const int lkb    = (lane >> 4) * 16;
    const uint32_t a_lane = sb + A_OFF + (uint32_t)((wm * 64 + lrow16) * ROW_BYTES + lkb);
    const uint32_t b_off  = (uint32_t)((wn * 32 + lrow16) * ROW_BYTES + lkb);

    int it, jt;
    map_u(t0, it, jt);
    int i0    = it * TILE_M;
    int rslot = c - chunk_of(strip_start(it));

    issue_tile(sb + A_OFF, i0, tid);
    issue_tile(sb + ((t0 & 1) ? B1_OFF : B0_OFF), map_jt(t0) * TILE_M, tid);
    CP_COMMIT();
    issue_tile(sb + ((t0 & 1) ? B0_OFF : B1_OFF), map_jt(t0 + 1) * TILE_M, tid);
    CP_COMMIT();

    int labr[8];
    #pragma unroll
    for (int s = 0; s < 8; s++)
        labr[s] = lab_buf[i0 + wm * 64 + (s >> 1) * 16 + (s & 1) * 8 + (lane >> 2)];

    float sall[8] = {0,0,0,0,0,0,0,0};
    float spos[8] = {0,0,0,0,0,0,0,0};
    float acc[4][4][4];

    #pragma unroll 1
    for (int u = t0; u < t1; u++) {
        int nit, njt;
        map_u(u, nit, njt);
        const uint32_t b_lane = sb + ((u & 1) ? B1_OFF : B0_OFF) + b_off;

        if (nit != it) {
            // row change: flush, switch strip, reload A (drains B FIFO too)
            flush_rows(smem, sall, spos, i0, rslot, wm, wn, lane, tid);
            it    = nit;
            i0    = it * TILE_M;
            rslot = c - chunk_of(strip_start(it));
            #pragma unroll
            for (int s = 0; s < 8; s++)
                labr[s] = lab_buf[i0 + wm * 64 + (s >> 1) * 16 + (s & 1) * 8 + (lane >> 2)];
            CP_WAIT(0);
            __syncthreads();
            issue_tile(sb + A_OFF, i0, tid);
            CP_COMMIT();
            CP_WAIT(0);
            __syncthreads();
        } else {
            if (u == t1 - 1) { CP_WAIT(0); } else { CP_WAIT(1); }
            __syncthreads();
        }
        jt = njt;

        mma_tile(acc, a_lane, b_lane);

        __syncthreads();
        if (u + 2 < t1) {
            issue_tile(sb + ((u & 1) ? B1_OFF : B0_OFF), map_jt(u + 2) * TILE_M, tid);
            CP_COMMIT();
        }

        if (jt == it) epilogue<true >(acc, i0, it, jt, wm, wn, lane, labr, sall, spos);
        else          epilogue<false>(acc, i0, it, jt, wm, wn, lane, labr, sall, spos);
    }

    flush_rows(smem, sall, spos, i0, rslot, wm, wn, lane, tid);
}

// ============================================================================
// Kernel 3 (fused): per-row loss + last-block total.
// Block blk covers rows of column tile jt = blk: col slots [0, 2*jt) only.
// ============================================================================
__global__ void finalize_kernel(float* __restrict__ out) {
    __shared__ float red[128];
    __shared__ bool  is_last;
    const int blk = blockIdx.x;
    const int i   = blk * 128 + threadIdx.x;
    const int jt  = blk;

    float a0 = 0.f, p0 = 0.f, a1 = 0.f, p1 = 0.f;
    #pragma unroll
    for (int s = 0; s < 8; s++) {
        a0 += scratch[PR_ALL + (size_t)s * N_TOT + i];
        p0 += scratch[PR_POS + (size_t)s * N_TOT + i];
    }
    const int nslots = 2 * jt;
    #pragma unroll 4
    for (int s = 0; s < nslots; s++) {
        if (s & 1) {
            a1 += scratch[PC_ALL + (size_t)s * N_TOT + i];
            p1 += scratch[PC_POS + (size_t)s * N_TOT + i];
        } else {
            a0 += scratch[PC_ALL + (size_t)s * N_TOT + i];
            p0 += scratch[PC_POS + (size_t)s * N_TOT + i];
        }
    }
    float a = a0 + a1, p = p0 + p1;
    red[threadIdx.x] = logf(a) - logf(p);
    __syncthreads();
    #pragma unroll
    for (int o = 64; o > 0; o >>= 1) {
        if (threadIdx.x < o) red[threadIdx.x] += red[threadIdx.x + o];
        __syncthreads();
    }
    if (threadIdx.x == 0) {
        blocksum[blk] = red[0];
        __threadfence();
        unsigned int t = atomicInc(&fin_counter, 63);
        is_last = (t == 63);
    }
    __syncthreads();
    if (is_last) {
        float s = (threadIdx.x < 64) ? blocksum[threadIdx.x] : 0.f;
        red[threadIdx.x] = s;
        __syncthreads();
        #pragma unroll
        for (int o = 64; o > 0; o >>= 1) {
            if (threadIdx.x < o) red[threadIdx.x] += red[threadIdx.x + o];
            __syncthreads();
        }
        if (threadIdx.x == 0) out[0] = red[0];
    }
}

// ============================================================================
extern "C" void kernel_launch(void* const* d_in, const int* in_sizes, int n_in,
                              void* d_out, int out_size) {
    const float* feats  = (const float*)d_in[0];
    const float* posf   = (const float*)d_in[1];
    const int*   labels = (const int*)d_in[2];

    prep_kernel<<<N_TOT / 8, 256>>>(feats, posf, labels);

    cudaFuncSetAttribute(milnce_mma_kernel,
                         cudaFuncAttributeMaxDynamicSharedMemorySize, SMEM_TOTAL);
    milnce_mma_kernel<<<NCTA, 256, SMEM_TOTAL>>>();

    finalize_kernel<<<64, 128>>>((float*)d_out);
}

// round 10
// speedup vs baseline: 3.3964x; 1.0004x over previous
#include <cuda_runtime.h>
#include <cuda_bf16.h>
#include <cstdint>

#define N_TOT   8192
#define D_DIM   256
#define TILE_M  128
#define B_HALF  4096
#define NROWT   64
#define K_STEPS 16
#define NTILES  2080
#define NCTA    148

#define ROW_BYTES 528
#define A_OFF   0
#define B0_OFF  (TILE_M * ROW_BYTES)
#define B1_OFF  (B0_OFF + TILE_M * ROW_BYTES)
#define RED_OFF (B1_OFF + TILE_M * ROW_BYTES)
#define SMEM_TOTAL (RED_OFF + 128 * 4 * 2 * 4)

// -------- device scratch --------
__device__ __align__(16) __nv_bfloat16 g_bf[N_TOT * D_DIM];
__device__ int   lab_buf[N_TOT];

#define PR_ALL  0
#define PR_POS  (8 * N_TOT)
#define PC_ALL  (16 * N_TOT)
#define PC_POS  (PC_ALL + 128 * N_TOT)
#define SCRATCH_FLOATS (PC_POS + 128 * N_TOT)
__device__ __align__(16) float scratch[SCRATCH_FLOATS];
__device__ float blocksum[64];
__device__ unsigned int fin_counter = 0;

// ======================= helpers =======================
static __device__ __forceinline__ uint32_t smem_u32(const void* p) {
    uint32_t a;
    asm("{ .reg .u64 t; cvta.to.shared.u64 t, %1; cvt.u32.u64 %0, t; }" : "=r"(a) : "l"(p));
    return a;
}
static __device__ __forceinline__ float ex2f(float x) {
    float r; asm("ex2.approx.ftz.f32 %0, %1;" : "=f"(r) : "f"(x)); return r;
}
static __device__ __forceinline__ uint32_t pack_bf2(float lo, float hi) {
    uint32_t r; asm("cvt.rn.bf16x2.f32 %0, %1, %2;" : "=r"(r) : "f"(hi), "f"(lo)); return r;
}
static __device__ __forceinline__ void cp16(uint32_t saddr, const void* g) {
    asm volatile("cp.async.cg.shared.global [%0], [%1], 16;" :: "r"(saddr), "l"(g) : "memory");
}
#define CP_COMMIT() asm volatile("cp.async.commit_group;" ::: "memory")
#define CP_WAIT(n)  asm volatile("cp.async.wait_group %0;" :: "n"(n) : "memory")

static __device__ __forceinline__ void ldsm_x4(uint32_t& r0, uint32_t& r1,
                                               uint32_t& r2, uint32_t& r3, uint32_t a) {
    asm volatile("ldmatrix.sync.aligned.m8n8.x4.shared.b16 {%0,%1,%2,%3}, [%4];"
                 : "=r"(r0), "=r"(r1), "=r"(r2), "=r"(r3) : "r"(a));
}
static __device__ __forceinline__ void mma16816(float* d, const uint32_t* a,
                                                uint32_t b0, uint32_t b1) {
    asm volatile(
        "mma.sync.aligned.m16n8k16.row.col.f32.bf16.bf16.f32 "
        "{%0,%1,%2,%3}, {%4,%5,%6,%7}, {%8,%9}, {%0,%1,%2,%3};"
        : "+f"(d[0]), "+f"(d[1]), "+f"(d[2]), "+f"(d[3])
        : "r"(a[0]), "r"(a[1]), "r"(a[2]), "r"(a[3]), "r"(b0), "r"(b1));
}

// ---- schedule mapping (pair order: [64][1][63][2]...[33][32]) ----
static __device__ __forceinline__ void map_u(int u, int& it, int& jt) {
    int p = u / 65, off = u - p * 65;
    int l0 = 64 - p;
    if (off < l0) { it = p;      jt = p + off; }
    else          { it = 63 - p; jt = (63 - p) + (off - l0); }
}
static __device__ __forceinline__ int map_jt(int u) {
    int it, jt; map_u(u, it, jt); return jt;
}
static __device__ __forceinline__ int chunk_of(int u) {
    return (u < 120) ? (u / 15) : (8 + (u - 120) / 14);
}
static __device__ __forceinline__ int strip_start(int it) {
    int p = (it < 32) ? it : 63 - it;
    return (it < 32) ? (65 * p) : (65 * p + (64 - p));
}
static __device__ __forceinline__ int strip_end(int it) {
    return (it < 32) ? (65 * it + (64 - it)) : (65 * (63 - it) + 65);
}

// ============================================================================
// Kernel 1: normalize -> bf16, labels, zero the row-slot scratch.
// ============================================================================
__global__ void prep_kernel(const float* __restrict__ feats,
                            const float* __restrict__ posf,
                            const int* __restrict__ labels) {
    int row  = blockIdx.x * 8 + (threadIdx.x >> 5);
    int lane = threadIdx.x & 31;
    const float* src = (row < B_HALF) ? (feats + (size_t)row * D_DIM)
                                      : (posf + (size_t)(row - B_HALF) * D_DIM);
    const float4* s4 = reinterpret_cast<const float4*>(src);
    float4 v0 = s4[lane];
    float4 v1 = s4[lane + 32];
    float ss = v0.x*v0.x + v0.y*v0.y + v0.z*v0.z + v0.w*v0.w
             + v1.x*v1.x + v1.y*v1.y + v1.z*v1.z + v1.w*v1.w;
    #pragma unroll
    for (int off = 16; off > 0; off >>= 1)
        ss += __shfl_xor_sync(0xffffffffu, ss, off);
    float inv = rsqrtf(ss);
    uint2 o0, o1;
    o0.x = pack_bf2(v0.x * inv, v0.y * inv);
    o0.y = pack_bf2(v0.z * inv, v0.w * inv);
    o1.x = pack_bf2(v1.x * inv, v1.y * inv);
    o1.y = pack_bf2(v1.z * inv, v1.w * inv);
    uint2* dst = reinterpret_cast<uint2*>(g_bf + (size_t)row * D_DIM);
    dst[lane]      = o0;
    dst[lane + 32] = o1;
    if (lane == 0)
        lab_buf[row] = labels[(row < B_HALF) ? row : row - B_HALF];

    int gidx = blockIdx.x * blockDim.x + threadIdx.x;
    if (gidx < (16 * N_TOT) / 4)
        reinterpret_cast<float4*>(scratch)[gidx] = make_float4(0.f, 0.f, 0.f, 0.f);
}

static __device__ __forceinline__ void issue_tile(uint32_t sbuf, int row0, int tid) {
    const uint4* src = reinterpret_cast<const uint4*>(g_bf);
    #pragma unroll
    for (int t = 0; t < 16; t++) {
        int id = tid + t * 256;
        int r  = id >> 5;
        int kc = id & 31;
        cp16(sbuf + r * ROW_BYTES + kc * 16, src + (size_t)(row0 + r) * 32 + kc);
    }
}

static __device__ __forceinline__ void mma_tile(float (&acc)[4][4][4],
                                                uint32_t a_lane, uint32_t b_lane) {
    #pragma unroll
    for (int ms = 0; ms < 4; ms++)
        #pragma unroll
        for (int ns = 0; ns < 4; ns++)
            #pragma unroll
            for (int c = 0; c < 4; c++) acc[ms][ns][c] = 0.f;

    #pragma unroll 2
    for (int ks = 0; ks < K_STEPS; ks++) {
        const uint32_t koff = (uint32_t)(ks * 32);
        uint32_t a[4][4];
        #pragma unroll
        for (int ms = 0; ms < 4; ms++)
            ldsm_x4(a[ms][0], a[ms][1], a[ms][2], a[ms][3],
                    a_lane + (uint32_t)(ms * 16 * ROW_BYTES) + koff);
        uint32_t b[2][4];
        #pragma unroll
        for (int p = 0; p < 2; p++)
            ldsm_x4(b[p][0], b[p][1], b[p][2], b[p][3],
                    b_lane + (uint32_t)(p * 16 * ROW_BYTES) + koff);
        #pragma unroll
        for (int ms = 0; ms < 4; ms++) {
            mma16816(acc[ms][0], a[ms], b[0][0], b[0][2]);
            mma16816(acc[ms][1], a[ms], b[0][1], b[0][3]);
            mma16816(acc[ms][2], a[ms], b[1][0], b[1][2]);
            mma16816(acc[ms][3], a[ms], b[1][1], b[1][3]);
        }
    }
}

template <bool DIAG>
static __device__ __forceinline__ void epilogue(const float (&acc)[4][4][4],
        int i0, int it, int jt, int wm, int wn, int lane,
        const int (&labr)[8], float (&sall)[8], float (&spos)[8]) {
    const float K_EXP = 14.42695040888963f;
    const int jbase = jt * TILE_M;
    int labc[4][2];
    #pragma unroll
    for (int ns = 0; ns < 4; ns++) {
        int c0 = jbase + wn * 32 + ns * 8 + (lane & 3) * 2;
        labc[ns][0] = lab_buf[c0];
        labc[ns][1] = lab_buf[c0 + 1];
    }
    float ecall[8], ecpos[8];
    #pragma unroll
    for (int x = 0; x < 8; x++) { ecall[x] = 0.f; ecpos[x] = 0.f; }

    #pragma unroll
    for (int ms = 0; ms < 4; ms++) {
        const int gi_lo = i0 + wm * 64 + ms * 16 + (lane >> 2);
        #pragma unroll
        for (int ns = 0; ns < 4; ns++) {
            const int gj0 = jbase + wn * 32 + ns * 8 + (lane & 3) * 2;
            #pragma unroll
            for (int c = 0; c < 4; c++) {
                const int rh   = c >> 1;
                const int slot = ms * 2 + rh;
                const int b    = c & 1;
                float e = ex2f(acc[ms][ns][c] * K_EXP);
                bool match = (labc[ns][b] == labr[slot]);
                if (DIAG) {
                    if ((gi_lo + rh * 8) != (gj0 + b)) {
                        sall[slot] += e;
                        if (match) spos[slot] += e;
                    }
                } else {
                    sall[slot] += e;
                    ecall[ns * 2 + b] += e;
                    if (match) { spos[slot] += e; ecpos[ns * 2 + b] += e; }
                }
            }
        }
    }

    if (!DIAG) {
        #pragma unroll
        for (int x = 0; x < 8; x++) {
            #pragma unroll
            for (int off = 4; off < 32; off <<= 1) {
                ecall[x] += __shfl_xor_sync(0xffffffffu, ecall[x], off);
                ecpos[x] += __shfl_xor_sync(0xffffffffu, ecpos[x], off);
            }
        }
        if (lane < 4) {
            const int slot = it * 2 + wm;
            float2* pa = reinterpret_cast<float2*>(scratch + PC_ALL + (size_t)slot * N_TOT);
            float2* pp = reinterpret_cast<float2*>(scratch + PC_POS + (size_t)slot * N_TOT);
            #pragma unroll
            for (int ns = 0; ns < 4; ns++) {
                int cidx = (jbase + wn * 32 + ns * 8 + lane * 2) >> 1;
                pa[cidx] = make_float2(ecall[ns * 2], ecall[ns * 2 + 1]);
                pp[cidx] = make_float2(ecpos[ns * 2], ecpos[ns * 2 + 1]);
            }
        }
    }
}

static __device__ __forceinline__ void flush_rows(char* smem, float (&sall)[8],
        float (&spos)[8], int i0, int rslot, int wm, int wn, int lane, int tid) {
    #pragma unroll
    for (int s = 0; s < 8; s++) {
        sall[s] += __shfl_xor_sync(0xffffffffu, sall[s], 1);
        sall[s] += __shfl_xor_sync(0xffffffffu, sall[s], 2);
        spos[s] += __shfl_xor_sync(0xffffffffu, spos[s], 1);
        spos[s] += __shfl_xor_sync(0xffffffffu, spos[s], 2);
    }
    float* red_all = reinterpret_cast<float*>(smem + RED_OFF);
    float* red_pos = red_all + 128 * 4;
    __syncthreads();
    if ((lane & 3) == 0) {
        #pragma unroll
        for (int s = 0; s < 8; s++) {
            int rloc = wm * 64 + (s >> 1) * 16 + (s & 1) * 8 + (lane >> 2);
            red_all[rloc * 4 + wn] = sall[s];
            red_pos[rloc * 4 + wn] = spos[s];
        }
    }
    __syncthreads();
    if (tid < 128) {
        float a = red_all[tid * 4 + 0] + red_all[tid * 4 + 1]
                + red_all[tid * 4 + 2] + red_all[tid * 4 + 3];
        float p = red_pos[tid * 4 + 0] + red_pos[tid * 4 + 1]
                + red_pos[tid * 4 + 2] + red_pos[tid * 4 + 3];
        scratch[PR_ALL + (size_t)rslot * N_TOT + i0 + tid] = a;
        scratch[PR_POS + (size_t)rslot * N_TOT + i0 + tid] = p;
    }
    #pragma unroll
    for (int s = 0; s < 8; s++) { sall[s] = 0.f; spos[s] = 0.f; }
}

// ============================================================================
// Kernel 2: balanced 148-CTA symmetric HMMA gram, cross-tile pipelined:
// MMA(tile v) overlaps epilogue(tile v-1) via dual accumulator sets.
// ============================================================================
__global__ void __launch_bounds__(256, 1) milnce_mma_kernel() {
    extern __shared__ char smem[];
    const uint32_t sb = smem_u32(smem);

    const int tid  = threadIdx.x;
    const int wid  = tid >> 5;
    const int lane = tid & 31;
    const int wm   = wid >> 2;
    const int wn   = wid & 3;
    const int c    = blockIdx.x;

    const int t0 = (c < 8) ? c * 15 : 120 + (c - 8) * 14;
    const int t1 = t0 + ((c < 8) ? 15 : 14);

    const int lrow16 = (lane & 7) + ((lane >> 3) & 1) * 8;
    const int lkb    = (lane >> 4) * 16;
    const uint32_t a_lane = sb + A_OFF + (uint32_t)((wm * 64 + lrow16) * ROW_BYTES + lkb);
    const uint32_t b_off  = (uint32_t)((wn * 32 + lrow16) * ROW_BYTES + lkb);

    int it, jt0;
    map_u(t0, it, jt0);
    int i0    = it * TILE_M;
    int rslot = c - chunk_of(strip_start(it));

    issue_tile(sb + A_OFF, i0, tid);
    issue_tile(sb + ((t0 & 1) ? B1_OFF : B0_OFF), map_jt(t0) * TILE_M, tid);
    CP_COMMIT();
    issue_tile(sb + (((t0 + 1) & 1) ? B1_OFF : B0_OFF), map_jt(t0 + 1) * TILE_M, tid);
    CP_COMMIT();

    int labr[8];
    #pragma unroll
    for (int s = 0; s < 8; s++)
        labr[s] = lab_buf[i0 + wm * 64 + (s >> 1) * 16 + (s & 1) * 8 + (lane >> 2)];

    float sall[8] = {0,0,0,0,0,0,0,0};
    float spos[8] = {0,0,0,0,0,0,0,0};
    float accA[4][4][4], accB[4][4][4];

    // tile-step helpers
    auto b_lane_of = [&](int x) -> uint32_t {
        return sb + ((x & 1) ? B1_OFF : B0_OFF) + b_off;
    };
    auto wait_for = [&](int x) {
        if (x + 1 < t1) { CP_WAIT(1); } else { CP_WAIT(0); }
        __syncthreads();
    };
    auto post_mma = [&](int x) {   // after mma(x): free x's buffer, prefetch x+2
        __syncthreads();
        if (x + 2 < t1) {
            issue_tile(sb + ((x & 1) ? B1_OFF : B0_OFF), map_jt(x + 2) * TILE_M, tid);
            CP_COMMIT();
        }
    };
    auto do_epi = [&](const float (&acc)[4][4][4], int x) {
        int jtv = map_jt(x);
        if (jtv == it) epilogue<true >(acc, i0, it, jtv, wm, wn, lane, labr, sall, spos);
        else           epilogue<false>(acc, i0, it, jtv, wm, wn, lane, labr, sall, spos);
    };

    int u = t0;
    #pragma unroll 1
    while (u < t1) {
        const int s1 = min(t1, strip_end(it));

        // first tile of segment -> accA
        wait_for(u);
        mma_tile(accA, a_lane, b_lane_of(u));
        post_mma(u);

        int v = u + 1;
        #pragma unroll 1
        for (; v + 1 < s1; v += 2) {
            wait_for(v);
            mma_tile(accB, a_lane, b_lane_of(v));
            post_mma(v);
            do_epi(accA, v - 1);               // overlaps accB's HMMAs

            wait_for(v + 1);
            mma_tile(accA, a_lane, b_lane_of(v + 1));
            post_mma(v + 1);
            do_epi(accB, v);                   // overlaps accA's HMMAs
        }
        if (v < s1) {                          // one trailing tile -> accB
            wait_for(v);
            mma_tile(accB, a_lane, b_lane_of(v));
            post_mma(v);
            do_epi(accA, v - 1);
            do_epi(accB, v);
        } else {
            do_epi(accA, s1 - 1);
        }

        flush_rows(smem, sall, spos, i0, rslot, wm, wn, lane, tid);

        u = s1;
        if (u < t1) {
            int njt;
            map_u(u, it, njt);
            i0    = it * TILE_M;
            rslot = c - chunk_of(strip_start(it));
            #pragma unroll
            for (int s = 0; s < 8; s++)
                labr[s] = lab_buf[i0 + wm * 64 + (s >> 1) * 16 + (s & 1) * 8 + (lane >> 2)];
            CP_WAIT(0);
            __syncthreads();
            issue_tile(sb + A_OFF, i0, tid);
            CP_COMMIT();
            CP_WAIT(0);
            __syncthreads();
        }
    }
}

// ============================================================================
// Kernel 3 (fused): per-row loss + last-block total.
// ============================================================================
__global__ void finalize_kernel(float* __restrict__ out) {
    __shared__ float red[128];
    __shared__ bool  is_last;
    const int blk = blockIdx.x;
    const int i   = blk * 128 + threadIdx.x;
    const int jt  = blk;

    float a0 = 0.f, p0 = 0.f, a1 = 0.f, p1 = 0.f;
    #pragma unroll
    for (int s = 0; s < 8; s++) {
        a0 += scratch[PR_ALL + (size_t)s * N_TOT + i];
        p0 += scratch[PR_POS + (size_t)s * N_TOT + i];
    }
    const int nslots = 2 * jt;
    #pragma unroll 4
    for (int s = 0; s < nslots; s++) {
        if (s & 1) {
            a1 += scratch[PC_ALL + (size_t)s * N_TOT + i];
            p1 += scratch[PC_POS + (size_t)s * N_TOT + i];
        } else {
            a0 += scratch[PC_ALL + (size_t)s * N_TOT + i];
            p0 += scratch[PC_POS + (size_t)s * N_TOT + i];
        }
    }
    float a = a0 + a1, p = p0 + p1;
    red[threadIdx.x] = logf(a) - logf(p);
    __syncthreads();
    #pragma unroll
    for (int o = 64; o > 0; o >>= 1) {
        if (threadIdx.x < o) red[threadIdx.x] += red[threadIdx.x + o];
        __syncthreads();
    }
    if (threadIdx.x == 0) {
        blocksum[blk] = red[0];
        __threadfence();
        unsigned int t = atomicInc(&fin_counter, 63);
        is_last = (t == 63);
    }
    __syncthreads();
    if (is_last) {
        float s = (threadIdx.x < 64) ? blocksum[threadIdx.x] : 0.f;
        red[threadIdx.x] = s;
        __syncthreads();
        #pragma unroll
        for (int o = 64; o > 0; o >>= 1) {
            if (threadIdx.x < o) red[threadIdx.x] += red[threadIdx.x + o];
            __syncthreads();
        }
        if (threadIdx.x == 0) out[0] = red[0];
    }
}

// ============================================================================
extern "C" void kernel_launch(void* const* d_in, const int* in_sizes, int n_in,
                              void* d_out, int out_size) {
    const float* feats  = (const float*)d_in[0];
    const float* posf   = (const float*)d_in[1];
    const int*   labels = (const int*)d_in[2];

    prep_kernel<<<N_TOT / 8, 256>>>(feats, posf, labels);

    cudaFuncSetAttribute(milnce_mma_kernel,
                         cudaFuncAttributeMaxDynamicSharedMemorySize, SMEM_TOTAL);
    milnce_mma_kernel<<<NCTA, 256, SMEM_TOTAL>>>();

    finalize_kernel<<<64, 128>>>((float*)d_out);
}